// round 15
// baseline (speedup 1.0000x reference)
#include <cuda_runtime.h>
#include <cuda_fp16.h>

#define NMAX 50000
#define DDIM 128
#define EMAX 800000
#define CAP  64
#define OVF_CAP 8192

// ---------------- device-global scratch (allocation-free rule) -------------
// NOTE: g_cnt starts zero (static init) and is re-zeroed by gather_kernel
// after each use, so no per-call zeroing pass is needed.
__device__ float g_xj[NMAX * DDIM];   // lrelu(x0 W2^T + b2), fp32
__device__ float g_e1[NMAX];          // exp(-a1)
__device__ float g_e2[NMAX];          // exp(-a2)
__device__ int   g_idx_is_64;
__device__ int   g_cnt[NMAX];
__device__ int   g_tbl[NMAX * CAP];
__device__ int   g_ovf_cnt;
__device__ long long g_ovf[OVF_CAP];
// fp16 split weights, combined [256][128] row-major (rows 0-127 = W1, 128-255 = W2)
__device__ __align__(16) __half g_wh[256 * DDIM];
__device__ __align__(16) __half g_wl[256 * DDIM];

__device__ __forceinline__ unsigned pack_h2(float a, float b) {
    __half2 t = __floats2half2_rn(a, b);
    return *reinterpret_cast<unsigned*>(&t);
}
__device__ __forceinline__ unsigned smem_u32(const void* p) {
    unsigned r;
    asm("{ .reg .u64 t; cvta.to.shared.u64 t, %1; cvt.u32.u64 %0, t; }" : "=r"(r) : "l"(p));
    return r;
}
__device__ __forceinline__ void ldm_x4(unsigned* r, unsigned addr) {
    asm volatile("ldmatrix.sync.aligned.m8n8.x4.shared.b16 {%0,%1,%2,%3}, [%4];"
                 : "=r"(r[0]), "=r"(r[1]), "=r"(r[2]), "=r"(r[3]) : "r"(addr));
}
__device__ __forceinline__ void mma16816(float* d, const unsigned* a, const unsigned* b) {
    asm volatile("mma.sync.aligned.m16n8k16.row.col.f32.f16.f16.f32 "
                 "{%0,%1,%2,%3}, {%4,%5,%6,%7}, {%8,%9}, {%0,%1,%2,%3};"
                 : "+f"(d[0]), "+f"(d[1]), "+f"(d[2]), "+f"(d[3])
                 : "r"(a[0]), "r"(a[1]), "r"(a[2]), "r"(a[3]), "r"(b[0]), "r"(b[1]));
}
__device__ __forceinline__ void cp16(unsigned saddr, const void* gptr) {
    asm volatile("cp.async.cg.shared.global [%0], [%1], 16;"
                 :: "r"(saddr), "l"(gptr) : "memory");
}

// ---------------------------------------------------------------------------
// Prep: dtype probe + ovf-counter reset (block 0) + coalesced W fp16 split.
// No g_cnt zeroing (gather maintains the zeroed invariant).
// ---------------------------------------------------------------------------
__global__ __launch_bounds__(512)
void prep_kernel(const int* __restrict__ ei32,
                 const float* __restrict__ W1, const float* __restrict__ W2)
{
    int id = blockIdx.x * 512 + threadIdx.x;
    if (blockIdx.x == 0 && threadIdx.x < 32) {
        int lane = threadIdx.x;
        int v = ei32[1 + 2 * lane] | ei32[65 + 2 * lane];
        unsigned m = __ballot_sync(0xffffffffu, v == 0);
        if (lane == 0) g_idx_is_64 = (m == 0xffffffffu) ? 1 : 0;
    }
    if (blockIdx.x == 0 && threadIdx.x == 33) g_ovf_cnt = 0;
    if (id < 256 * DDIM) {
        int c = id >> 7, k = id & 127;
        float w = (c < DDIM) ? W1[c * DDIM + k] : W2[(c - DDIM) * DDIM + k];
        __half h = __float2half_rn(w);
        g_wh[id] = h;
        g_wl[id] = __float2half_rn(w - __half2float(h));
    }
}

__global__ __launch_bounds__(256)
void scatter_build_kernel(const void* __restrict__ ei_raw, int E)
{
    int i = blockIdx.x * blockDim.x + threadIdx.x;
    if (i >= E) return;
    int src, dst;
    if (g_idx_is_64) {
        const long long* e = (const long long*)ei_raw;
        src = (int)e[i];
        dst = (int)e[(long long)E + i];
    } else {
        const int* e = (const int*)ei_raw;
        src = e[i];
        dst = e[E + i];
    }
    int pos = atomicAdd(&g_cnt[src], 1);
    if (pos < CAP) {
        g_tbl[src * CAP + pos] = dst;
    } else {
        int o = atomicAdd(&g_ovf_cnt, 1);
        if (o < OVF_CAP)
            g_ovf[o] = ((long long)src << 32) | (unsigned int)dst;
    }
}

// ---------------------------------------------------------------------------
// GEMM (R11-exact): fp16 2-product HMMA, 128 rows/CTA, whole-K single stage.
// 512 threads = 16 warps (4x4), warp tile 32x64.
// cols 0..127 -> Y1 (a1), 128..255 -> Y2 (g_xj + a2).
// ---------------------------------------------------------------------------
#define RS       272
#define SA_OFF   0
#define SB_H     34816
#define SB_LD    69632
#define P_OFF    174080
#define RED_OFF  176128
#define SMEM_TOT 177152

__global__ __launch_bounds__(512, 1)
void gemm_mma_kernel(const float* __restrict__ x0,
                     const float* __restrict__ b1, const float* __restrict__ b2,
                     const float* __restrict__ a1w, const float* __restrict__ a1b,
                     const float* __restrict__ a2w, const float* __restrict__ a2b,
                     int n)
{
    extern __shared__ __align__(16) char sm[];
    const unsigned sb = smem_u32(sm);
    const int tid  = threadIdx.x;
    const int wid  = tid >> 5;
    const int lane = tid & 31;
    const int wr   = wid & 3;
    const int wc   = wid >> 2;
    const int row0 = blockIdx.x * 128;

    float* s_b1  = (float*)(sm + P_OFF);
    float* s_b2  = (float*)(sm + P_OFF + 512);
    float* s_a1w = (float*)(sm + P_OFF + 1024);
    float* s_a2w = (float*)(sm + P_OFF + 1536);
    float* s_r1  = (float*)(sm + RED_OFF);
    float* s_r2  = (float*)(sm + RED_OFF + 512);

    if (tid < 128) {
        s_b1[tid] = b1[tid]; s_b2[tid] = b2[tid];
        s_a1w[tid] = a1w[tid]; s_a2w[tid] = a2w[tid];
        s_r1[tid] = 0.f; s_r2[tid] = 0.f;
    }

    // ---- B stage via cp.async ----
    {
        const char* srch = (const char*)g_wh;
        const char* srcl = (const char*)g_wl;
#pragma unroll
        for (int j = 0; j < 8; j++) {
            int id  = tid + 512 * j;
            int row = id >> 4;
            int ch  = id & 15;
            unsigned dst = sb + SB_H + row * RS + ch * 16;
            cp16(dst,         srch + row * 256 + ch * 16);
            cp16(dst + SB_LD, srcl + row * 256 + ch * 16);
        }
    }
    asm volatile("cp.async.commit_group;" ::: "memory");

    // ---- A stage: fp32 -> fp16 ----
    {
        int row  = tid >> 2;
        int seg  = tid & 3;
        int grow = row0 + row;
        const float4* xr = reinterpret_cast<const float4*>(x0 + (size_t)grow * DDIM);
#pragma unroll
        for (int g = 0; g < 8; g++) {
            int q = seg * 8 + g;
            float4 v = (grow < n) ? xr[q] : make_float4(0.f, 0.f, 0.f, 0.f);
            uint2 hv;
            hv.x = pack_h2(v.x, v.y); hv.y = pack_h2(v.z, v.w);
            *reinterpret_cast<uint2*>(sm + SA_OFF + row * RS + q * 8) = hv;
        }
    }
    asm volatile("cp.async.wait_group 0;" ::: "memory");
    __syncthreads();

    // ---- MMA mainloop: 8 k-steps of 16, 2 products (wh + wl) ----
    float acc[2][8][4];
#pragma unroll
    for (int i = 0; i < 2; i++)
#pragma unroll
        for (int j = 0; j < 8; j++)
#pragma unroll
            for (int q = 0; q < 4; q++) acc[i][j][q] = 0.f;

#pragma unroll
    for (int ks = 0; ks < 8; ks++) {
        unsigned ah[2][4];
        unsigned abase = sb + SA_OFF + (wr * 32 + (lane & 15)) * RS
                       + ks * 32 + (lane >> 4) * 16;
#pragma unroll
        for (int mt = 0; mt < 2; mt++)
            ldm_x4(ah[mt], abase + mt * 16 * RS);

        unsigned bbase = sb + SB_H
                       + (wc * 64 + ((lane >> 4) * 8) + (lane & 7)) * RS
                       + ks * 32 + (((lane >> 3) & 1) * 16);
#pragma unroll
        for (int np = 0; np < 4; np++) {
            unsigned bh[2][2], bl[2][2];
            ldm_x4(&bh[0][0], bbase + np * 16 * RS);
            ldm_x4(&bl[0][0], bbase + np * 16 * RS + SB_LD);
#pragma unroll
            for (int mt = 0; mt < 2; mt++)
#pragma unroll
                for (int j = 0; j < 2; j++) {
                    mma16816(acc[mt][2 * np + j], ah[mt], bh[j]);
                    mma16816(acc[mt][2 * np + j], ah[mt], bl[j]);
                }
        }
    }
    __syncthreads();

    // ---- epilogue ----
    const int qlane = lane >> 2;
    const int cpair = lane & 3;
    const int isY2  = (wc >= 2);
    const float* sbias = isY2 ? s_b2 : s_b1;
    const float* saw   = isY2 ? s_a2w : s_a1w;

#pragma unroll
    for (int mt = 0; mt < 2; mt++) {
        int lr0 = wr * 32 + mt * 16 + qlane;
        int lr1 = lr0 + 8;
        int gr0 = row0 + lr0, gr1 = row0 + lr1;
        float pr0 = 0.f, pr1 = 0.f;
#pragma unroll
        for (int nt = 0; nt < 8; nt++) {
            int cb = wc * 64 + nt * 8 + 2 * cpair;
            int c  = isY2 ? (cb - 128) : cb;
            float y00 = acc[mt][nt][0] + sbias[c];
            float y01 = acc[mt][nt][1] + sbias[c + 1];
            float y10 = acc[mt][nt][2] + sbias[c];
            float y11 = acc[mt][nt][3] + sbias[c + 1];
            y00 = (y00 >= 0.f) ? y00 : 0.2f * y00;
            y01 = (y01 >= 0.f) ? y01 : 0.2f * y01;
            y10 = (y10 >= 0.f) ? y10 : 0.2f * y10;
            y11 = (y11 >= 0.f) ? y11 : 0.2f * y11;
            pr0 += y00 * saw[c] + y01 * saw[c + 1];
            pr1 += y10 * saw[c] + y11 * saw[c + 1];
            if (isY2) {
                if (gr0 < n)
                    *reinterpret_cast<float2*>(&g_xj[(size_t)gr0 * DDIM + c]) =
                        make_float2(y00, y01);
                if (gr1 < n)
                    *reinterpret_cast<float2*>(&g_xj[(size_t)gr1 * DDIM + c]) =
                        make_float2(y10, y11);
            }
        }
#pragma unroll
        for (int off = 1; off < 4; off <<= 1) {
            pr0 += __shfl_xor_sync(0xffffffffu, pr0, off);
            pr1 += __shfl_xor_sync(0xffffffffu, pr1, off);
        }
        if (cpair == 0) {
            float* red = isY2 ? s_r2 : s_r1;
            atomicAdd(&red[lr0], pr0);
            atomicAdd(&red[lr1], pr1);
        }
    }
    __syncthreads();

    if (tid < 128) {
        int grow = row0 + tid;
        if (grow < n) {
            g_e1[grow] = __expf(-(s_r1[tid] + a1b[0]));
            g_e2[grow] = __expf(-(s_r2[tid] + a2b[0]));
        }
    }
}

// ---------------------------------------------------------------------------
// Gather (R11-exact core): one warp per src node, chunk-of-8, fp32 rows,
// 32-bit offsets; overflow inline; RE-ZEROES g_cnt for the next call.
// ---------------------------------------------------------------------------
__global__ __launch_bounds__(256)
void gather_kernel(const float* __restrict__ x0, float* __restrict__ out, int n)
{
    int gw   = (blockIdx.x * blockDim.x + threadIdx.x) >> 5;
    int lane = threadIdx.x & 31;
    if (gw >= n) return;

    int deg0 = g_cnt[gw];
    if (lane == 0) g_cnt[gw] = 0;          // maintain zeroed invariant
    int deg = (deg0 > CAP) ? CAP : deg0;
    const float e1 = g_e1[gw];
    const int* tbl = g_tbl + (unsigned)gw * CAP;
    const char* xjb = (const char*)g_xj;
    const unsigned lo = (unsigned)lane * 16u;

    float4 acc = make_float4(0.f, 0.f, 0.f, 0.f);

    for (int base = 0; base < deg; base += 8) {
        int4 q0 = *reinterpret_cast<const int4*>(tbl + base);
        int4 q1 = *reinterpret_cast<const int4*>(tbl + base + 4);
        unsigned id[8] = {(unsigned)q0.x, (unsigned)q0.y, (unsigned)q0.z, (unsigned)q0.w,
                          (unsigned)q1.x, (unsigned)q1.y, (unsigned)q1.z, (unsigned)q1.w};
        float att[8];
#pragma unroll
        for (int j = 0; j < 8; j++) att[j] = g_e2[id[j]];
#pragma unroll
        for (int j = 0; j < 8; j++)
            att[j] = (base + j < deg)
                   ? __fdividef(1.f, 1.f + e1 * att[j]) : 0.f;
        float4 v[8];
#pragma unroll
        for (int j = 0; j < 8; j++)
            v[j] = *reinterpret_cast<const float4*>(xjb + (id[j] * 512u + lo));
#pragma unroll
        for (int j = 0; j < 8; j++) {
            acc.x += att[j] * v[j].x;
            acc.y += att[j] * v[j].y;
            acc.z += att[j] * v[j].z;
            acc.w += att[j] * v[j].w;
        }
    }

    if (deg0 > CAP) {
        int nov = g_ovf_cnt;
        if (nov > OVF_CAP) nov = OVF_CAP;
        for (int i = 0; i < nov; i++) {
            long long p = g_ovf[i];
            if ((int)(p >> 32) == gw) {
                unsigned dst = (unsigned)(p & 0xffffffffll);
                float att = __fdividef(1.f, 1.f + e1 * g_e2[dst]);
                float4 v = *reinterpret_cast<const float4*>(xjb + (dst * 512u + lo));
                acc.x += att * v.x; acc.y += att * v.y;
                acc.z += att * v.z; acc.w += att * v.w;
            }
        }
    }

    float4 r = reinterpret_cast<const float4*>(x0 + (size_t)gw * DDIM)[lane];
    reinterpret_cast<float4*>(out + (size_t)gw * DDIM)[lane] =
        make_float4(r.x + acc.x, r.y + acc.y, r.z + acc.z, r.w + acc.w);
}

// ---------------------------------------------------------------------------
// Launcher (single stream). Inputs: x0, x1(unused), edge_index([2,E]),
//   W1, b1, W2, b2, a1_w, a1_b, a2_w, a2_b
// ---------------------------------------------------------------------------
extern "C" void kernel_launch(void* const* d_in, const int* in_sizes, int n_in,
                              void* d_out, int out_size)
{
    const float* x0  = (const float*)d_in[0];
    const void*  ei  = d_in[2];
    const float* W1  = (const float*)d_in[3];
    const float* b1  = (const float*)d_in[4];
    const float* W2  = (const float*)d_in[5];
    const float* b2  = (const float*)d_in[6];
    const float* a1w = (const float*)d_in[7];
    const float* a1b = (const float*)d_in[8];
    const float* a2w = (const float*)d_in[9];
    const float* a2b = (const float*)d_in[10];
    float* out = (float*)d_out;

    const int n = in_sizes[0] / DDIM;   // 50000
    const int E = in_sizes[2] / 2;      // 800000

    static int cfg_done = 0;
    if (!cfg_done) {
        cudaFuncSetAttribute(gemm_mma_kernel,
                             cudaFuncAttributeMaxDynamicSharedMemorySize, SMEM_TOT);
        cfg_done = 1;
    }

    prep_kernel<<<(256 * DDIM + 511) / 512, 512>>>((const int*)ei, W1, W2);
    scatter_build_kernel<<<(E + 255) / 256, 256>>>(ei, E);

    int gblocks = (n + 127) / 128;      // 391
    gemm_mma_kernel<<<gblocks, 512, SMEM_TOT>>>(x0, b1, b2, a1w, a1b, a2w, a2b, n);

    int gthreads = n * 32;
    gather_kernel<<<(gthreads + 255) / 256, 256>>>(x0, out, n);
}

// round 16
// speedup vs baseline: 2.0806x; 2.0806x over previous
#include <cuda_runtime.h>
#include <cuda_fp16.h>

#define NMAX 50000
#define DDIM 128
#define EMAX 800000
#define CAP  64
#define OVF_CAP 8192

// ---------------- device-global scratch (allocation-free rule) -------------
__device__ float g_xj[NMAX * DDIM];   // lrelu(x0 W2^T + b2), fp32
__device__ float g_e1[NMAX];          // exp(-a1)
__device__ float g_e2[NMAX];          // exp(-a2)
__device__ int   g_idx_is_64;
__device__ int   g_cnt[NMAX];
__device__ int   g_tbl[NMAX * CAP];
__device__ int   g_ovf_cnt;
__device__ long long g_ovf[OVF_CAP];
// fp16 split weights, combined [256][128] row-major (rows 0-127 = W1, 128-255 = W2)
__device__ __align__(16) __half g_wh[256 * DDIM];
__device__ __align__(16) __half g_wl[256 * DDIM];

__device__ __forceinline__ unsigned pack_h2(float a, float b) {
    __half2 t = __floats2half2_rn(a, b);
    return *reinterpret_cast<unsigned*>(&t);
}
__device__ __forceinline__ unsigned smem_u32(const void* p) {
    unsigned r;
    asm("{ .reg .u64 t; cvta.to.shared.u64 t, %1; cvt.u32.u64 %0, t; }" : "=r"(r) : "l"(p));
    return r;
}
__device__ __forceinline__ void ldm_x4(unsigned* r, unsigned addr) {
    asm volatile("ldmatrix.sync.aligned.m8n8.x4.shared.b16 {%0,%1,%2,%3}, [%4];"
                 : "=r"(r[0]), "=r"(r[1]), "=r"(r[2]), "=r"(r[3]) : "r"(addr));
}
__device__ __forceinline__ void mma16816(float* d, const unsigned* a, const unsigned* b) {
    asm volatile("mma.sync.aligned.m16n8k16.row.col.f32.f16.f16.f32 "
                 "{%0,%1,%2,%3}, {%4,%5,%6,%7}, {%8,%9}, {%0,%1,%2,%3};"
                 : "+f"(d[0]), "+f"(d[1]), "+f"(d[2]), "+f"(d[3])
                 : "r"(a[0]), "r"(a[1]), "r"(a[2]), "r"(a[3]), "r"(b[0]), "r"(b[1]));
}
__device__ __forceinline__ void cp16(unsigned saddr, const void* gptr) {
    asm volatile("cp.async.cg.shared.global [%0], [%1], 16;"
                 :: "r"(saddr), "l"(gptr) : "memory");
}

// ---------------------------------------------------------------------------
// Fused prep (R11-exact): dtype probe + zero counters + W fp16 hi/lo split
// ---------------------------------------------------------------------------
__global__ __launch_bounds__(512)
void fused_prep_kernel(const int* __restrict__ ei32,
                       const float* __restrict__ W1, const float* __restrict__ W2, int n)
{
    int id = blockIdx.x * 512 + threadIdx.x;
    if (blockIdx.x == 0 && threadIdx.x < 32) {
        int lane = threadIdx.x;
        int v = ei32[1 + 2 * lane] | ei32[65 + 2 * lane];
        unsigned m = __ballot_sync(0xffffffffu, v == 0);
        if (lane == 0) g_idx_is_64 = (m == 0xffffffffu) ? 1 : 0;
    }
    if (blockIdx.x == 0 && threadIdx.x == 33) g_ovf_cnt = 0;
    if (id < n) g_cnt[id] = 0;
    if (id < 256 * DDIM) {
        int c = id >> 7, k = id & 127;
        float w = (c < DDIM) ? W1[c * DDIM + k] : W2[(c - DDIM) * DDIM + k];
        __half h = __float2half_rn(w);
        g_wh[id] = h;
        g_wl[id] = __float2half_rn(w - __half2float(h));
    }
}

// ---------------------------------------------------------------------------
// Bucket build: 2 edges per thread, paired index loads (halves load instrs)
// ---------------------------------------------------------------------------
__device__ __forceinline__ void tbl_insert(int src, int dst)
{
    int pos = atomicAdd(&g_cnt[src], 1);
    if (pos < CAP) {
        g_tbl[src * CAP + pos] = dst;
    } else {
        int o = atomicAdd(&g_ovf_cnt, 1);
        if (o < OVF_CAP)
            g_ovf[o] = ((long long)src << 32) | (unsigned int)dst;
    }
}

__global__ __launch_bounds__(256)
void scatter_build_kernel(const void* __restrict__ ei_raw, int E)
{
    int i0 = (blockIdx.x * blockDim.x + threadIdx.x) * 2;
    if (i0 >= E) return;
    bool two = (i0 + 1 < E);
    int s0, d0, s1 = 0, d1 = 0;
    if (g_idx_is_64) {
        const long long* e = (const long long*)ei_raw;
        if (two) {
            longlong2 sp = *reinterpret_cast<const longlong2*>(e + i0);
            longlong2 dp = *reinterpret_cast<const longlong2*>(e + (long long)E + i0);
            s0 = (int)sp.x; s1 = (int)sp.y;
            d0 = (int)dp.x; d1 = (int)dp.y;
        } else {
            s0 = (int)e[i0]; d0 = (int)e[(long long)E + i0];
        }
    } else {
        const int* e = (const int*)ei_raw;
        if (two) {
            int2 sp = *reinterpret_cast<const int2*>(e + i0);
            int2 dp = *reinterpret_cast<const int2*>(e + E + i0);
            s0 = sp.x; s1 = sp.y; d0 = dp.x; d1 = dp.y;
        } else {
            s0 = e[i0]; d0 = e[E + i0];
        }
    }
    tbl_insert(s0, d0);
    if (two) tbl_insert(s1, d1);
}

// ---------------------------------------------------------------------------
// GEMM (R11-exact): fp16 2-product HMMA, 128 rows/CTA, whole-K single stage.
// 512 threads = 16 warps (4x4), warp tile 32x64.
// cols 0..127 -> Y1 (a1), 128..255 -> Y2 (g_xj + a2).
// ---------------------------------------------------------------------------
#define RS       272
#define SA_OFF   0
#define SB_H     34816
#define SB_LD    69632
#define P_OFF    174080
#define RED_OFF  176128
#define SMEM_TOT 177152

__global__ __launch_bounds__(512, 1)
void gemm_mma_kernel(const float* __restrict__ x0,
                     const float* __restrict__ b1, const float* __restrict__ b2,
                     const float* __restrict__ a1w, const float* __restrict__ a1b,
                     const float* __restrict__ a2w, const float* __restrict__ a2b,
                     int n)
{
    extern __shared__ __align__(16) char sm[];
    const unsigned sb = smem_u32(sm);
    const int tid  = threadIdx.x;
    const int wid  = tid >> 5;
    const int lane = tid & 31;
    const int wr   = wid & 3;
    const int wc   = wid >> 2;
    const int row0 = blockIdx.x * 128;

    float* s_b1  = (float*)(sm + P_OFF);
    float* s_b2  = (float*)(sm + P_OFF + 512);
    float* s_a1w = (float*)(sm + P_OFF + 1024);
    float* s_a2w = (float*)(sm + P_OFF + 1536);
    float* s_r1  = (float*)(sm + RED_OFF);
    float* s_r2  = (float*)(sm + RED_OFF + 512);

    if (tid < 128) {
        s_b1[tid] = b1[tid]; s_b2[tid] = b2[tid];
        s_a1w[tid] = a1w[tid]; s_a2w[tid] = a2w[tid];
        s_r1[tid] = 0.f; s_r2[tid] = 0.f;
    }

    // ---- B stage via cp.async ----
    {
        const char* srch = (const char*)g_wh;
        const char* srcl = (const char*)g_wl;
#pragma unroll
        for (int j = 0; j < 8; j++) {
            int id  = tid + 512 * j;
            int row = id >> 4;
            int ch  = id & 15;
            unsigned dst = sb + SB_H + row * RS + ch * 16;
            cp16(dst,         srch + row * 256 + ch * 16);
            cp16(dst + SB_LD, srcl + row * 256 + ch * 16);
        }
    }
    asm volatile("cp.async.commit_group;" ::: "memory");

    // ---- A stage: fp32 -> fp16 ----
    {
        int row  = tid >> 2;
        int seg  = tid & 3;
        int grow = row0 + row;
        const float4* xr = reinterpret_cast<const float4*>(x0 + (size_t)grow * DDIM);
#pragma unroll
        for (int g = 0; g < 8; g++) {
            int q = seg * 8 + g;
            float4 v = (grow < n) ? xr[q] : make_float4(0.f, 0.f, 0.f, 0.f);
            uint2 hv;
            hv.x = pack_h2(v.x, v.y); hv.y = pack_h2(v.z, v.w);
            *reinterpret_cast<uint2*>(sm + SA_OFF + row * RS + q * 8) = hv;
        }
    }
    asm volatile("cp.async.wait_group 0;" ::: "memory");
    __syncthreads();

    // ---- MMA mainloop: 8 k-steps of 16, 2 products (wh + wl) ----
    float acc[2][8][4];
#pragma unroll
    for (int i = 0; i < 2; i++)
#pragma unroll
        for (int j = 0; j < 8; j++)
#pragma unroll
            for (int q = 0; q < 4; q++) acc[i][j][q] = 0.f;

#pragma unroll
    for (int ks = 0; ks < 8; ks++) {
        unsigned ah[2][4];
        unsigned abase = sb + SA_OFF + (wr * 32 + (lane & 15)) * RS
                       + ks * 32 + (lane >> 4) * 16;
#pragma unroll
        for (int mt = 0; mt < 2; mt++)
            ldm_x4(ah[mt], abase + mt * 16 * RS);

        unsigned bbase = sb + SB_H
                       + (wc * 64 + ((lane >> 4) * 8) + (lane & 7)) * RS
                       + ks * 32 + (((lane >> 3) & 1) * 16);
#pragma unroll
        for (int np = 0; np < 4; np++) {
            unsigned bh[2][2], bl[2][2];
            ldm_x4(&bh[0][0], bbase + np * 16 * RS);
            ldm_x4(&bl[0][0], bbase + np * 16 * RS + SB_LD);
#pragma unroll
            for (int mt = 0; mt < 2; mt++)
#pragma unroll
                for (int j = 0; j < 2; j++) {
                    mma16816(acc[mt][2 * np + j], ah[mt], bh[j]);
                    mma16816(acc[mt][2 * np + j], ah[mt], bl[j]);
                }
        }
    }
    __syncthreads();

    // ---- epilogue ----
    const int qlane = lane >> 2;
    const int cpair = lane & 3;
    const int isY2  = (wc >= 2);
    const float* sbias = isY2 ? s_b2 : s_b1;
    const float* saw   = isY2 ? s_a2w : s_a1w;

#pragma unroll
    for (int mt = 0; mt < 2; mt++) {
        int lr0 = wr * 32 + mt * 16 + qlane;
        int lr1 = lr0 + 8;
        int gr0 = row0 + lr0, gr1 = row0 + lr1;
        float pr0 = 0.f, pr1 = 0.f;
#pragma unroll
        for (int nt = 0; nt < 8; nt++) {
            int cb = wc * 64 + nt * 8 + 2 * cpair;
            int c  = isY2 ? (cb - 128) : cb;
            float y00 = acc[mt][nt][0] + sbias[c];
            float y01 = acc[mt][nt][1] + sbias[c + 1];
            float y10 = acc[mt][nt][2] + sbias[c];
            float y11 = acc[mt][nt][3] + sbias[c + 1];
            y00 = (y00 >= 0.f) ? y00 : 0.2f * y00;
            y01 = (y01 >= 0.f) ? y01 : 0.2f * y01;
            y10 = (y10 >= 0.f) ? y10 : 0.2f * y10;
            y11 = (y11 >= 0.f) ? y11 : 0.2f * y11;
            pr0 += y00 * saw[c] + y01 * saw[c + 1];
            pr1 += y10 * saw[c] + y11 * saw[c + 1];
            if (isY2) {
                if (gr0 < n)
                    *reinterpret_cast<float2*>(&g_xj[(size_t)gr0 * DDIM + c]) =
                        make_float2(y00, y01);
                if (gr1 < n)
                    *reinterpret_cast<float2*>(&g_xj[(size_t)gr1 * DDIM + c]) =
                        make_float2(y10, y11);
            }
        }
#pragma unroll
        for (int off = 1; off < 4; off <<= 1) {
            pr0 += __shfl_xor_sync(0xffffffffu, pr0, off);
            pr1 += __shfl_xor_sync(0xffffffffu, pr1, off);
        }
        if (cpair == 0) {
            float* red = isY2 ? s_r2 : s_r1;
            atomicAdd(&red[lr0], pr0);
            atomicAdd(&red[lr1], pr1);
        }
    }
    __syncthreads();

    if (tid < 128) {
        int grow = row0 + tid;
        if (grow < n) {
            g_e1[grow] = __expf(-(s_r1[tid] + a1b[0]));
            g_e2[grow] = __expf(-(s_r2[tid] + a2b[0]));
        }
    }
}

// ---------------------------------------------------------------------------
// Gather (R11-exact): one warp per src node, chunk-of-8, fp32 rows,
// 32-bit offsets; overflow (deg > CAP, ~never) handled inline.
// ---------------------------------------------------------------------------
__global__ __launch_bounds__(256)
void gather_kernel(const float* __restrict__ x0, float* __restrict__ out, int n)
{
    int gw   = (blockIdx.x * blockDim.x + threadIdx.x) >> 5;
    int lane = threadIdx.x & 31;
    if (gw >= n) return;

    int deg0 = g_cnt[gw];
    int deg = (deg0 > CAP) ? CAP : deg0;
    const float e1 = g_e1[gw];
    const int* tbl = g_tbl + (unsigned)gw * CAP;
    const char* xjb = (const char*)g_xj;
    const unsigned lo = (unsigned)lane * 16u;

    float4 acc = make_float4(0.f, 0.f, 0.f, 0.f);

    for (int base = 0; base < deg; base += 8) {
        int4 q0 = *reinterpret_cast<const int4*>(tbl + base);
        int4 q1 = *reinterpret_cast<const int4*>(tbl + base + 4);
        unsigned id[8] = {(unsigned)q0.x, (unsigned)q0.y, (unsigned)q0.z, (unsigned)q0.w,
                          (unsigned)q1.x, (unsigned)q1.y, (unsigned)q1.z, (unsigned)q1.w};
        float att[8];
#pragma unroll
        for (int j = 0; j < 8; j++) att[j] = g_e2[id[j]];
#pragma unroll
        for (int j = 0; j < 8; j++)
            att[j] = (base + j < deg)
                   ? __fdividef(1.f, 1.f + e1 * att[j]) : 0.f;
        float4 v[8];
#pragma unroll
        for (int j = 0; j < 8; j++)
            v[j] = *reinterpret_cast<const float4*>(xjb + (id[j] * 512u + lo));
#pragma unroll
        for (int j = 0; j < 8; j++) {
            acc.x += att[j] * v[j].x;
            acc.y += att[j] * v[j].y;
            acc.z += att[j] * v[j].z;
            acc.w += att[j] * v[j].w;
        }
    }

    if (deg0 > CAP) {
        int nov = g_ovf_cnt;
        if (nov > OVF_CAP) nov = OVF_CAP;
        for (int i = 0; i < nov; i++) {
            long long p = g_ovf[i];
            if ((int)(p >> 32) == gw) {
                unsigned dst = (unsigned)(p & 0xffffffffll);
                float att = __fdividef(1.f, 1.f + e1 * g_e2[dst]);
                float4 v = *reinterpret_cast<const float4*>(xjb + (dst * 512u + lo));
                acc.x += att * v.x; acc.y += att * v.y;
                acc.z += att * v.z; acc.w += att * v.w;
            }
        }
    }

    float4 r = reinterpret_cast<const float4*>(x0 + (size_t)gw * DDIM)[lane];
    reinterpret_cast<float4*>(out + (size_t)gw * DDIM)[lane] =
        make_float4(r.x + acc.x, r.y + acc.y, r.z + acc.z, r.w + acc.w);
}

// ---------------------------------------------------------------------------
// Launcher (single stream). Inputs: x0, x1(unused), edge_index([2,E]),
//   W1, b1, W2, b2, a1_w, a1_b, a2_w, a2_b
// ---------------------------------------------------------------------------
extern "C" void kernel_launch(void* const* d_in, const int* in_sizes, int n_in,
                              void* d_out, int out_size)
{
    const float* x0  = (const float*)d_in[0];
    const void*  ei  = d_in[2];
    const float* W1  = (const float*)d_in[3];
    const float* b1  = (const float*)d_in[4];
    const float* W2  = (const float*)d_in[5];
    const float* b2  = (const float*)d_in[6];
    const float* a1w = (const float*)d_in[7];
    const float* a1b = (const float*)d_in[8];
    const float* a2w = (const float*)d_in[9];
    const float* a2b = (const float*)d_in[10];
    float* out = (float*)d_out;

    const int n = in_sizes[0] / DDIM;   // 50000
    const int E = in_sizes[2] / 2;      // 800000

    static int cfg_done = 0;
    if (!cfg_done) {
        cudaFuncSetAttribute(gemm_mma_kernel,
                             cudaFuncAttributeMaxDynamicSharedMemorySize, SMEM_TOT);
        cfg_done = 1;
    }

    fused_prep_kernel<<<(n + 511) / 512, 512>>>((const int*)ei, W1, W2, n);
    scatter_build_kernel<<<(E / 2 + 255) / 256, 256>>>(ei, E);

    int gblocks = (n + 127) / 128;      // 391
    gemm_mma_kernel<<<gblocks, 512, SMEM_TOT>>>(x0, b1, b2, a1w, a1b, a2w, a2b, n);

    int gthreads = n * 32;
    gather_kernel<<<(gthreads + 255) / 256, 256>>>(x0, out, n);
}

// round 17
// speedup vs baseline: 2.2926x; 1.1019x over previous
#include <cuda_runtime.h>
#include <cuda_fp16.h>

#define NMAX 50000
#define DDIM 128
#define EMAX 800000
#define CAP  64
#define OVF_CAP 8192

// ---------------- device-global scratch (allocation-free rule) -------------
__device__ float g_xj[NMAX * DDIM];   // lrelu(x0 W2^T + b2), fp32
__device__ float g_e1[NMAX];          // exp(-a1)
__device__ float g_e2[NMAX];          // exp(-a2)
__device__ int   g_idx_is_64;
__device__ int   g_cnt[NMAX];
__device__ int   g_tbl[NMAX * CAP];
__device__ int   g_ovf_cnt;
__device__ long long g_ovf[OVF_CAP];
// fp16 weights, combined [256][128] row-major (rows 0-127 = W1, 128-255 = W2)
__device__ __align__(16) __half g_wh[256 * DDIM];

__device__ __forceinline__ unsigned pack_h2(float a, float b) {
    __half2 t = __floats2half2_rn(a, b);
    return *reinterpret_cast<unsigned*>(&t);
}
__device__ __forceinline__ unsigned smem_u32(const void* p) {
    unsigned r;
    asm("{ .reg .u64 t; cvta.to.shared.u64 t, %1; cvt.u32.u64 %0, t; }" : "=r"(r) : "l"(p));
    return r;
}
__device__ __forceinline__ void ldm_x4(unsigned* r, unsigned addr) {
    asm volatile("ldmatrix.sync.aligned.m8n8.x4.shared.b16 {%0,%1,%2,%3}, [%4];"
                 : "=r"(r[0]), "=r"(r[1]), "=r"(r[2]), "=r"(r[3]) : "r"(addr));
}
__device__ __forceinline__ void mma16816(float* d, const unsigned* a, const unsigned* b) {
    asm volatile("mma.sync.aligned.m16n8k16.row.col.f32.f16.f16.f32 "
                 "{%0,%1,%2,%3}, {%4,%5,%6,%7}, {%8,%9}, {%0,%1,%2,%3};"
                 : "+f"(d[0]), "+f"(d[1]), "+f"(d[2]), "+f"(d[3])
                 : "r"(a[0]), "r"(a[1]), "r"(a[2]), "r"(a[3]), "r"(b[0]), "r"(b[1]));
}
__device__ __forceinline__ void cp16(unsigned saddr, const void* gptr) {
    asm volatile("cp.async.cg.shared.global [%0], [%1], 16;"
                 :: "r"(saddr), "l"(gptr) : "memory");
}

// ---------------------------------------------------------------------------
// Fused prep: dtype probe + zero counters + W fp16 convert (single)
// ---------------------------------------------------------------------------
__global__ __launch_bounds__(512)
void fused_prep_kernel(const int* __restrict__ ei32,
                       const float* __restrict__ W1, const float* __restrict__ W2, int n)
{
    int id = blockIdx.x * 512 + threadIdx.x;
    if (blockIdx.x == 0 && threadIdx.x < 32) {
        int lane = threadIdx.x;
        int v = ei32[1 + 2 * lane] | ei32[65 + 2 * lane];
        unsigned m = __ballot_sync(0xffffffffu, v == 0);
        if (lane == 0) g_idx_is_64 = (m == 0xffffffffu) ? 1 : 0;
    }
    if (blockIdx.x == 0 && threadIdx.x == 33) g_ovf_cnt = 0;
    if (id < n) g_cnt[id] = 0;
    if (id < 256 * DDIM) {
        int c = id >> 7, k = id & 127;
        float w = (c < DDIM) ? W1[c * DDIM + k] : W2[(c - DDIM) * DDIM + k];
        g_wh[id] = __float2half_rn(w);
    }
}

// ---------------------------------------------------------------------------
// Bucket build (R16-exact): 2 edges per thread, paired index loads
// ---------------------------------------------------------------------------
__device__ __forceinline__ void tbl_insert(int src, int dst)
{
    int pos = atomicAdd(&g_cnt[src], 1);
    if (pos < CAP) {
        g_tbl[src * CAP + pos] = dst;
    } else {
        int o = atomicAdd(&g_ovf_cnt, 1);
        if (o < OVF_CAP)
            g_ovf[o] = ((long long)src << 32) | (unsigned int)dst;
    }
}

__global__ __launch_bounds__(256)
void scatter_build_kernel(const void* __restrict__ ei_raw, int E)
{
    int i0 = (blockIdx.x * blockDim.x + threadIdx.x) * 2;
    if (i0 >= E) return;
    bool two = (i0 + 1 < E);
    int s0, d0, s1 = 0, d1 = 0;
    if (g_idx_is_64) {
        const long long* e = (const long long*)ei_raw;
        if (two) {
            longlong2 sp = *reinterpret_cast<const longlong2*>(e + i0);
            longlong2 dp = *reinterpret_cast<const longlong2*>(e + (long long)E + i0);
            s0 = (int)sp.x; s1 = (int)sp.y;
            d0 = (int)dp.x; d1 = (int)dp.y;
        } else {
            s0 = (int)e[i0]; d0 = (int)e[(long long)E + i0];
        }
    } else {
        const int* e = (const int*)ei_raw;
        if (two) {
            int2 sp = *reinterpret_cast<const int2*>(e + i0);
            int2 dp = *reinterpret_cast<const int2*>(e + E + i0);
            s0 = sp.x; s1 = sp.y; d0 = dp.x; d1 = dp.y;
        } else {
            s0 = e[i0]; d0 = e[E + i0];
        }
    }
    tbl_insert(s0, d0);
    if (two) tbl_insert(s1, d1);
}

// ---------------------------------------------------------------------------
// GEMM: single-product fp16 HMMA (x fp16 * W fp16), 128 rows/CTA, whole-K.
// 512 threads = 16 warps (4x4), warp tile 32x64.
// cols 0..127 -> Y1 (a1), 128..255 -> Y2 (g_xj + a2).
// smem 107.5KB (A 34816 + B 69632 + params/red)
// ---------------------------------------------------------------------------
#define RS       272
#define SA_OFF   0                 // A: 128*272 = 34816 (fp16)
#define SB_H     34816             // B: 256*272 = 69632 (fp16, single)
#define P_OFF    104448            // b1,b2,a1w,a2w: 4*512
#define RED_OFF  106496            // r1,r2: 2*512
#define SMEM_TOT 107520

__global__ __launch_bounds__(512, 1)
void gemm_mma_kernel(const float* __restrict__ x0,
                     const float* __restrict__ b1, const float* __restrict__ b2,
                     const float* __restrict__ a1w, const float* __restrict__ a1b,
                     const float* __restrict__ a2w, const float* __restrict__ a2b,
                     int n)
{
    extern __shared__ __align__(16) char sm[];
    const unsigned sb = smem_u32(sm);
    const int tid  = threadIdx.x;
    const int wid  = tid >> 5;
    const int lane = tid & 31;
    const int wr   = wid & 3;
    const int wc   = wid >> 2;
    const int row0 = blockIdx.x * 128;

    float* s_b1  = (float*)(sm + P_OFF);
    float* s_b2  = (float*)(sm + P_OFF + 512);
    float* s_a1w = (float*)(sm + P_OFF + 1024);
    float* s_a2w = (float*)(sm + P_OFF + 1536);
    float* s_r1  = (float*)(sm + RED_OFF);
    float* s_r2  = (float*)(sm + RED_OFF + 512);

    if (tid < 128) {
        s_b1[tid] = b1[tid]; s_b2[tid] = b2[tid];
        s_a1w[tid] = a1w[tid]; s_a2w[tid] = a2w[tid];
        s_r1[tid] = 0.f; s_r2[tid] = 0.f;
    }

    // ---- B stage via cp.async: 256 rows x 128 fp16 ----
    {
        const char* srch = (const char*)g_wh;
#pragma unroll
        for (int j = 0; j < 8; j++) {
            int id  = tid + 512 * j;
            int row = id >> 4;
            int ch  = id & 15;
            cp16(sb + SB_H + row * RS + ch * 16, srch + row * 256 + ch * 16);
        }
    }
    asm volatile("cp.async.commit_group;" ::: "memory");

    // ---- A stage: fp32 -> fp16 ----
    {
        int row  = tid >> 2;
        int seg  = tid & 3;
        int grow = row0 + row;
        const float4* xr = reinterpret_cast<const float4*>(x0 + (size_t)grow * DDIM);
#pragma unroll
        for (int g = 0; g < 8; g++) {
            int q = seg * 8 + g;
            float4 v = (grow < n) ? xr[q] : make_float4(0.f, 0.f, 0.f, 0.f);
            uint2 hv;
            hv.x = pack_h2(v.x, v.y); hv.y = pack_h2(v.z, v.w);
            *reinterpret_cast<uint2*>(sm + SA_OFF + row * RS + q * 8) = hv;
        }
    }
    asm volatile("cp.async.wait_group 0;" ::: "memory");
    __syncthreads();

    // ---- MMA mainloop: 8 k-steps of 16, single product ----
    float acc[2][8][4];
#pragma unroll
    for (int i = 0; i < 2; i++)
#pragma unroll
        for (int j = 0; j < 8; j++)
#pragma unroll
            for (int q = 0; q < 4; q++) acc[i][j][q] = 0.f;

#pragma unroll
    for (int ks = 0; ks < 8; ks++) {
        unsigned ah[2][4];
        unsigned abase = sb + SA_OFF + (wr * 32 + (lane & 15)) * RS
                       + ks * 32 + (lane >> 4) * 16;
#pragma unroll
        for (int mt = 0; mt < 2; mt++)
            ldm_x4(ah[mt], abase + mt * 16 * RS);

        unsigned bbase = sb + SB_H
                       + (wc * 64 + ((lane >> 4) * 8) + (lane & 7)) * RS
                       + ks * 32 + (((lane >> 3) & 1) * 16);
#pragma unroll
        for (int np = 0; np < 4; np++) {
            unsigned bh[2][2];
            ldm_x4(&bh[0][0], bbase + np * 16 * RS);
#pragma unroll
            for (int mt = 0; mt < 2; mt++)
#pragma unroll
                for (int j = 0; j < 2; j++)
                    mma16816(acc[mt][2 * np + j], ah[mt], bh[j]);
        }
    }
    __syncthreads();

    // ---- epilogue ----
    const int qlane = lane >> 2;
    const int cpair = lane & 3;
    const int isY2  = (wc >= 2);
    const float* sbias = isY2 ? s_b2 : s_b1;
    const float* saw   = isY2 ? s_a2w : s_a1w;

#pragma unroll
    for (int mt = 0; mt < 2; mt++) {
        int lr0 = wr * 32 + mt * 16 + qlane;
        int lr1 = lr0 + 8;
        int gr0 = row0 + lr0, gr1 = row0 + lr1;
        float pr0 = 0.f, pr1 = 0.f;
#pragma unroll
        for (int nt = 0; nt < 8; nt++) {
            int cb = wc * 64 + nt * 8 + 2 * cpair;
            int c  = isY2 ? (cb - 128) : cb;
            float y00 = acc[mt][nt][0] + sbias[c];
            float y01 = acc[mt][nt][1] + sbias[c + 1];
            float y10 = acc[mt][nt][2] + sbias[c];
            float y11 = acc[mt][nt][3] + sbias[c + 1];
            y00 = (y00 >= 0.f) ? y00 : 0.2f * y00;
            y01 = (y01 >= 0.f) ? y01 : 0.2f * y01;
            y10 = (y10 >= 0.f) ? y10 : 0.2f * y10;
            y11 = (y11 >= 0.f) ? y11 : 0.2f * y11;
            pr0 += y00 * saw[c] + y01 * saw[c + 1];
            pr1 += y10 * saw[c] + y11 * saw[c + 1];
            if (isY2) {
                if (gr0 < n)
                    *reinterpret_cast<float2*>(&g_xj[(size_t)gr0 * DDIM + c]) =
                        make_float2(y00, y01);
                if (gr1 < n)
                    *reinterpret_cast<float2*>(&g_xj[(size_t)gr1 * DDIM + c]) =
                        make_float2(y10, y11);
            }
        }
#pragma unroll
        for (int off = 1; off < 4; off <<= 1) {
            pr0 += __shfl_xor_sync(0xffffffffu, pr0, off);
            pr1 += __shfl_xor_sync(0xffffffffu, pr1, off);
        }
        if (cpair == 0) {
            float* red = isY2 ? s_r2 : s_r1;
            atomicAdd(&red[lr0], pr0);
            atomicAdd(&red[lr1], pr1);
        }
    }
    __syncthreads();

    if (tid < 128) {
        int grow = row0 + tid;
        if (grow < n) {
            g_e1[grow] = __expf(-(s_r1[tid] + a1b[0]));
            g_e2[grow] = __expf(-(s_r2[tid] + a2b[0]));
        }
    }
}

// ---------------------------------------------------------------------------
// Gather (R16-exact): one warp per src node, chunk-of-8, fp32 rows,
// 32-bit offsets; overflow (deg > CAP, ~never) handled inline.
// ---------------------------------------------------------------------------
__global__ __launch_bounds__(256)
void gather_kernel(const float* __restrict__ x0, float* __restrict__ out, int n)
{
    int gw   = (blockIdx.x * blockDim.x + threadIdx.x) >> 5;
    int lane = threadIdx.x & 31;
    if (gw >= n) return;

    int deg0 = g_cnt[gw];
    int deg = (deg0 > CAP) ? CAP : deg0;
    const float e1 = g_e1[gw];
    const int* tbl = g_tbl + (unsigned)gw * CAP;
    const char* xjb = (const char*)g_xj;
    const unsigned lo = (unsigned)lane * 16u;

    float4 acc = make_float4(0.f, 0.f, 0.f, 0.f);

    for (int base = 0; base < deg; base += 8) {
        int4 q0 = *reinterpret_cast<const int4*>(tbl + base);
        int4 q1 = *reinterpret_cast<const int4*>(tbl + base + 4);
        unsigned id[8] = {(unsigned)q0.x, (unsigned)q0.y, (unsigned)q0.z, (unsigned)q0.w,
                          (unsigned)q1.x, (unsigned)q1.y, (unsigned)q1.z, (unsigned)q1.w};
        float att[8];
#pragma unroll
        for (int j = 0; j < 8; j++) att[j] = g_e2[id[j]];
#pragma unroll
        for (int j = 0; j < 8; j++)
            att[j] = (base + j < deg)
                   ? __fdividef(1.f, 1.f + e1 * att[j]) : 0.f;
        float4 v[8];
#pragma unroll
        for (int j = 0; j < 8; j++)
            v[j] = *reinterpret_cast<const float4*>(xjb + (id[j] * 512u + lo));
#pragma unroll
        for (int j = 0; j < 8; j++) {
            acc.x += att[j] * v[j].x;
            acc.y += att[j] * v[j].y;
            acc.z += att[j] * v[j].z;
            acc.w += att[j] * v[j].w;
        }
    }

    if (deg0 > CAP) {
        int nov = g_ovf_cnt;
        if (nov > OVF_CAP) nov = OVF_CAP;
        for (int i = 0; i < nov; i++) {
            long long p = g_ovf[i];
            if ((int)(p >> 32) == gw) {
                unsigned dst = (unsigned)(p & 0xffffffffll);
                float att = __fdividef(1.f, 1.f + e1 * g_e2[dst]);
                float4 v = *reinterpret_cast<const float4*>(xjb + (dst * 512u + lo));
                acc.x += att * v.x; acc.y += att * v.y;
                acc.z += att * v.z; acc.w += att * v.w;
            }
        }
    }

    float4 r = reinterpret_cast<const float4*>(x0 + (size_t)gw * DDIM)[lane];
    reinterpret_cast<float4*>(out + (size_t)gw * DDIM)[lane] =
        make_float4(r.x + acc.x, r.y + acc.y, r.z + acc.z, r.w + acc.w);
}

// ---------------------------------------------------------------------------
// Launcher (single stream). Inputs: x0, x1(unused), edge_index([2,E]),
//   W1, b1, W2, b2, a1_w, a1_b, a2_w, a2_b
// ---------------------------------------------------------------------------
extern "C" void kernel_launch(void* const* d_in, const int* in_sizes, int n_in,
                              void* d_out, int out_size)
{
    const float* x0  = (const float*)d_in[0];
    const void*  ei  = d_in[2];
    const float* W1  = (const float*)d_in[3];
    const float* b1  = (const float*)d_in[4];
    const float* W2  = (const float*)d_in[5];
    const float* b2  = (const float*)d_in[6];
    const float* a1w = (const float*)d_in[7];
    const float* a1b = (const float*)d_in[8];
    const float* a2w = (const float*)d_in[9];
    const float* a2b = (const float*)d_in[10];
    float* out = (float*)d_out;

    const int n = in_sizes[0] / DDIM;   // 50000
    const int E = in_sizes[2] / 2;      // 800000

    static int cfg_done = 0;
    if (!cfg_done) {
        cudaFuncSetAttribute(gemm_mma_kernel,
                             cudaFuncAttributeMaxDynamicSharedMemorySize, SMEM_TOT);
        cfg_done = 1;
    }

    fused_prep_kernel<<<(n + 511) / 512, 512>>>((const int*)ei, W1, W2, n);
    scatter_build_kernel<<<(E / 2 + 255) / 256, 256>>>(ei, E);

    int gblocks = (n + 127) / 128;      // 391
    gemm_mma_kernel<<<gblocks, 512, SMEM_TOT>>>(x0, b1, b2, a1w, a1b, a2w, a2b, n);

    int gthreads = n * 32;
    gather_kernel<<<(gthreads + 255) / 256, 256>>>(x0, out, n);
}